// round 15
// baseline (speedup 1.0000x reference)
#include <cuda_runtime.h>
#include <cuda_fp16.h>
#include <cstdint>

#define TTOK 8192
#define DMODEL 1024
#define DFF 4096
#define NEXP 8
#define CAPACITY 2560
#define NSLOT (TTOK*2)
#define CLAMPV 10000.0f

// GEMM tiling: BM=128, BN=256, BK=64 (halves), 3-stage cp.async
#define PADH 72
#define ROWB 144
#define A_B (128*ROWB)               // 18432
#define B_B (256*ROWB)               // 36864
#define STG_B (A_B+B_B)              // 55296
#define NST 3
#define SMEM_BYTES (NST*STG_B)       // 165888

// ---------------- scratch ----------------
__device__ __half g_xnh[(size_t)TTOK*DMODEL];
__device__ __half g_w12h[(size_t)NEXP*2*DFF*DMODEL];
__device__ __half g_w3h[(size_t)NEXP*DMODEL*DFF];
__device__ __half g_h[(size_t)NEXP*CAPACITY*DFF];
__device__ int   g_slotExpert[NSLOT];
__device__ float g_slotWeight[NSLOT];
__device__ int   g_rowToken[NEXP*CAPACITY];
__device__ int   g_rowTok2[NEXP*CAPACITY];
__device__ float g_rowW[NEXP*CAPACITY];
__device__ __align__(16) int g_blockHist[64*8];  // zero at entry (module-load init; gemm1 e0=0 re-zeroes)
__device__ int   g_mcount[8];

// ---------------- helpers ----------------
__device__ __forceinline__ uint32_t smem_u32(const void* p){
  uint32_t a; asm("{ .reg .u64 t; cvta.to.shared.u64 t, %1; cvt.u32.u64 %0, t; }" : "=r"(a) : "l"(p));
  return a;
}
__device__ __forceinline__ void mma_f16(float* d, const uint32_t* a, uint32_t b0, uint32_t b1){
  asm volatile("mma.sync.aligned.m16n8k16.row.col.f32.f16.f16.f32 "
    "{%0,%1,%2,%3}, {%4,%5,%6,%7}, {%8,%9}, {%0,%1,%2,%3};\n"
    : "+f"(d[0]),"+f"(d[1]),"+f"(d[2]),"+f"(d[3])
    : "r"(a[0]),"r"(a[1]),"r"(a[2]),"r"(a[3]),"r"(b0),"r"(b1));
}
#define LDSM4(r0,r1,r2,r3,addr) \
  asm volatile("ldmatrix.sync.aligned.m8n8.x4.shared.b16 {%0,%1,%2,%3}, [%4];" \
    : "=r"(r0),"=r"(r1),"=r"(r2),"=r"(r3) : "r"(addr))
#define CPA(dst, src) \
  asm volatile("cp.async.cg.shared.global [%0], [%1], 16;" :: "r"(dst), "l"(src) : "memory")
#define CPA_COMMIT() asm volatile("cp.async.commit_group;" ::: "memory")
#define CPA_WAIT1()  asm volatile("cp.async.wait_group 1;" ::: "memory")

// ---------------- weight conversion (W12 4-expert half) ----------------
__global__ __launch_bounds__(256) void convw12_kernel(const float4* __restrict__ w12, int e0){
  const size_t N = (size_t)4*2*DFF*DMODEL/8;         // 4 experts' worth of 8-float groups
  const size_t base = (size_t)e0 * (2*DFF*DMODEL/8);
  size_t stride = (size_t)gridDim.x*blockDim.x;
  for (size_t i = (size_t)blockIdx.x*blockDim.x + threadIdx.x; i < N; i += stride){
    size_t j = base + i;
    float4 v0 = w12[j*2], v1 = w12[j*2+1];
    __half2* d = ((__half2*)g_w12h) + j*4;
    d[0] = __floats2half2_rn(v0.x, v0.y);
    d[1] = __floats2half2_rn(v0.z, v0.w);
    d[2] = __floats2half2_rn(v1.x, v1.y);
    d[3] = __floats2half2_rn(v1.z, v1.w);
  }
}
__global__ __launch_bounds__(256) void convw3_kernel(const float4* __restrict__ w3){
  const size_t N = (size_t)NEXP*DMODEL*DFF/8;
  size_t stride = (size_t)gridDim.x*blockDim.x;
  for (size_t i = (size_t)blockIdx.x*blockDim.x + threadIdx.x; i < N; i += stride){
    float4 v0 = w3[i*2], v1 = w3[i*2+1];
    __half2* d = ((__half2*)g_w3h) + i*4;
    d[0] = __floats2half2_rn(v0.x, v0.y);
    d[1] = __floats2half2_rn(v0.z, v0.w);
    d[2] = __floats2half2_rn(v1.x, v1.y);
    d[3] = __floats2half2_rn(v1.z, v1.w);
  }
}

// ---------------- LayerNorm + router + top-2 + fused hist ----------------
__global__ __launch_bounds__(256) void ln_router_kernel(
    const float* __restrict__ x, const float* __restrict__ gamma,
    const float* __restrict__ beta, const float* __restrict__ Wr)
{
  __shared__ float sx[DMODEL];
  __shared__ float rs[8], rss[8];
  __shared__ float slog[8];
  __shared__ float smu, srstd;
  int t = blockIdx.x, tid = threadIdx.x;
  int w = tid >> 5, lane = tid & 31;

  float4 v = ((const float4*)x)[(size_t)t*256 + tid];
  float s  = v.x+v.y+v.z+v.w;
  float ss = v.x*v.x+v.y*v.y+v.z*v.z+v.w*v.w;
  #pragma unroll
  for (int o=16;o>0;o>>=1){
    s  += __shfl_down_sync(0xffffffffu, s, o);
    ss += __shfl_down_sync(0xffffffffu, ss, o);
  }
  if (lane==0){ rs[w]=s; rss[w]=ss; }
  __syncthreads();
  if (tid==0){
    float S=0.f, SS=0.f;
    #pragma unroll
    for (int i=0;i<8;i++){ S+=rs[i]; SS+=rss[i]; }
    float mu = S * (1.0f/DMODEL);
    float var = SS * (1.0f/DMODEL) - mu*mu;
    smu = mu; srstd = rsqrtf(var + 1e-5f);
  }
  __syncthreads();
  float mu = smu, rstd = srstd;
  float4 gm = ((const float4*)gamma)[tid];
  float4 bt = ((const float4*)beta)[tid];
  float4 xn;
  xn.x = (v.x-mu)*rstd*gm.x + bt.x;
  xn.y = (v.y-mu)*rstd*gm.y + bt.y;
  xn.z = (v.z-mu)*rstd*gm.z + bt.z;
  xn.w = (v.w-mu)*rstd*gm.w + bt.w;
  ((float4*)sx)[tid] = xn;
  __half2 p0 = __floats2half2_rn(xn.x, xn.y);
  __half2 p1 = __floats2half2_rn(xn.z, xn.w);
  __half2* xp = (__half2*)(g_xnh + (size_t)t*DMODEL) + tid*2;
  xp[0]=p0; xp[1]=p1;
  __syncthreads();

  const float* wr = Wr + w*DMODEL;
  float acc = 0.f;
  for (int d=lane; d<DMODEL; d+=32) acc += sx[d]*wr[d];
  #pragma unroll
  for (int o=16;o>0;o>>=1) acc += __shfl_down_sync(0xffffffffu, acc, o);
  if (lane==0) slog[w] = fminf(fmaxf(acc, -CLAMPV), CLAMPV);
  __syncthreads();

  if (tid==0){
    float p[8];
    float m = slog[0];
    #pragma unroll
    for (int e=1;e<8;e++) m = fmaxf(m, slog[e]);
    float den=0.f;
    #pragma unroll
    for (int e=0;e<8;e++){ p[e]=expf(slog[e]-m); den+=p[e]; }
    float inv = 1.f/(den + 1e-12f);
    #pragma unroll
    for (int e=0;e<8;e++) p[e]*=inv;
    int i0=0;
    #pragma unroll
    for (int e=1;e<8;e++) if (p[e]>p[i0]) i0=e;
    int i1 = (i0==0)?1:0;
    #pragma unroll
    for (int e=0;e<8;e++) if (e!=i0 && p[e]>p[i1]) i1=e;
    g_slotExpert[2*t]   = i0; g_slotWeight[2*t]   = p[i0];
    g_slotExpert[2*t+1] = i1; g_slotWeight[2*t+1] = p[i1];
    int hb = (t >> 7) * 8;
    atomicAdd(&g_blockHist[hb + i0], 1);
    atomicAdd(&g_blockHist[hb + i1], 1);
  }
}

__global__ __launch_bounds__(256) void init_kernel(float4* __restrict__ out){
  int i = blockIdx.x*256 + threadIdx.x;
  out[i] = make_float4(0.f,0.f,0.f,0.f);
  if (i < NEXP*CAPACITY){ g_rowTok2[i] = -1; }
}

// ---------------- fused scan + stable rank ----------------
__global__ __launch_bounds__(256) void rank_kernel(){
  __shared__ int sHist[64][8];
  __shared__ int warpCnt[8][8];
  int tid = threadIdx.x, w = tid >> 5, lane = tid & 31;
  ((int2*)sHist)[tid] = ((const int2*)g_blockHist)[tid];
  if (tid < 64) ((int*)warpCnt)[tid] = 0;
  __syncthreads();

  int s = blockIdx.x*256 + tid;
  int e = g_slotExpert[s];
  unsigned mask = __match_any_sync(0xffffffffu, e);
  int before = __popc(mask & ((1u << lane) - 1u));
  if (lane == (__ffs(mask) - 1)) warpCnt[w][e] = __popc(mask);

  int gbase = 0;
  for (int b=0; b<blockIdx.x; b++) gbase += sHist[b][e];
  __syncthreads();
  int base = 0;
  #pragma unroll
  for (int ww=0; ww<8; ww++) if (ww < w) base += warpCnt[ww][e];
  int rank = gbase + base + before;
  if (rank < CAPACITY){
    int dest = e*CAPACITY + rank;
    g_rowToken[dest] = s >> 1;
    g_rowTok2[dest]  = s >> 1;
    g_rowW[dest]     = g_slotWeight[s];
  }

  if (blockIdx.x == 0 && tid < 8){
    int tot = 0;
    #pragma unroll
    for (int b=0; b<64; b++) tot += sHist[b][tid];
    g_mcount[tid] = (tot < CAPACITY) ? tot : CAPACITY;
  }
}

// ---------------- GEMM1 (4-expert half): (gathered xn) @ W12^T fp16, fused SwiGLU ----------------
// grid (20, 32, 4), block 256. tile 128 x (128 g | 128 u)
__global__ __launch_bounds__(256, 1) void gemm1_kernel(int e0){
  extern __shared__ __align__(16) char sdyn[];
  __shared__ int sTok[128];

  int e  = e0 + blockIdx.z;
  int m0 = blockIdx.x * 128;
  int tid = threadIdx.x, w = tid >> 5, lane = tid & 31;

  // reset histogram for next graph replay (before any early exit; ordered after rank)
  if (e0 == 0 && blockIdx.x == 0 && blockIdx.y == 0 && blockIdx.z == 0){
    g_blockHist[tid] = 0;
    g_blockHist[tid + 256] = 0;
  }

  if (m0 >= g_mcount[e]) return;
  int n0 = blockIdx.y * 128;

  if (tid < 128) sTok[tid] = g_rowToken[e*CAPACITY + m0 + tid];
  __syncthreads();

  uint32_t sbase = smem_u32(sdyn);
  int arow = tid >> 3, aseg = tid & 7;

  const __half* srcA[4];
  #pragma unroll
  for (int i=0;i<4;i++) srcA[i] = g_xnh + (size_t)sTok[arow + 32*i]*DMODEL + aseg*8;
  const __half* srcBg = g_w12h + ((size_t)e*2*DFF + n0 + arow)*DMODEL + aseg*8;
  const __half* srcBu = g_w12h + ((size_t)e*2*DFF + DFF + n0 + arow)*DMODEL + aseg*8;
  uint32_t dstA0 = (uint32_t)(arow*ROWB + aseg*16);
  uint32_t dstB0 = (uint32_t)(A_B + arow*ROWB + aseg*16);

#define G1_CPA(SB, KOFF) do{ \
  _Pragma("unroll") for (int i=0;i<4;i++) CPA((SB) + dstA0 + i*(32*ROWB), srcA[i] + (KOFF)); \
  _Pragma("unroll") for (int i=0;i<4;i++) CPA((SB) + dstB0 + i*(32*ROWB), srcBg + i*(32*DMODEL) + (KOFF)); \
  _Pragma("unroll") for (int i=0;i<4;i++) CPA((SB) + dstB0 + (i+4)*(32*ROWB), srcBu + i*(32*DMODEL) + (KOFF)); \
}while(0)

  const int KT = DMODEL/64;      // 16
  #pragma unroll
  for (int st=0; st<NST-1; st++){
    G1_CPA(sbase + (uint32_t)st*STG_B, st*64);
    CPA_COMMIT();
  }

  int wm = (w>>2)*64, wn = (w&3)*32;
  int gg = lane >> 2, tg = lane & 3;

  uint32_t offA[4];
  #pragma unroll
  for (int mi=0;mi<4;mi++)
    offA[mi] = (uint32_t)((wm + mi*16 + (lane&15))*PADH + (lane>>4)*8)*2u;
  uint32_t offBg[2], offBu[2];
  {
    int nrow = wn + ((lane>>4)&1)*8 + (lane&7);
    int kofl = ((lane>>3)&1)*8;
    #pragma unroll
    for (int p=0;p<2;p++){
      offBg[p] = (uint32_t)(A_B + ((nrow + p*16)*PADH + kofl)*2);
      offBu[p] = offBg[p] + (uint32_t)(128*PADH*2);
    }
  }

  float accG[4][4][4], accU[4][4][4];
  #pragma unroll
  for (int a=0;a<4;a++)
    #pragma unroll
    for (int b=0;b<4;b++)
      #pragma unroll
      for (int c=0;c<4;c++){ accG[a][b][c]=0.f; accU[a][b][c]=0.f; }

  uint32_t af[2][4][4], bgf[2][4][2], buf_[2][4][2];

#define G1_LOADF(B, KB) do{ \
  _Pragma("unroll") for (int mi=0;mi<4;mi++) \
    LDSM4(af[B][mi][0],af[B][mi][1],af[B][mi][2],af[B][mi][3], (KB) + offA[mi]); \
  _Pragma("unroll") for (int p=0;p<2;p++){ \
    LDSM4(bgf[B][2*p][0],bgf[B][2*p][1],bgf[B][2*p+1][0],bgf[B][2*p+1][1], (KB) + offBg[p]); \
    LDSM4(buf_[B][2*p][0],buf_[B][2*p][1],buf_[B][2*p+1][0],buf_[B][2*p+1][1], (KB) + offBu[p]); \
  } \
}while(0)

  int stage = 0, pstage = NST-1;
  for (int kt=0; kt<KT; ++kt){
    CPA_WAIT1();
    __syncthreads();
    if (kt+NST-1 < KT) G1_CPA(sbase + (uint32_t)pstage*STG_B, (kt+NST-1)*64);
    CPA_COMMIT();

    uint32_t sb = sbase + (uint32_t)stage*STG_B;
    G1_LOADF(0, sb);
    #pragma unroll
    for (int kk=0; kk<4; kk++){
      const int cur = kk & 1, nxt = cur ^ 1;
      if (kk < 3) G1_LOADF(nxt, sb + (kk+1)*32);
      #pragma unroll
      for (int ni=0;ni<4;ni++){
        #pragma unroll
        for (int mi=0;mi<4;mi++){
          mma_f16(accG[mi][ni], af[cur][mi], bgf[cur][ni][0], bgf[cur][ni][1]);
          mma_f16(accU[mi][ni], af[cur][mi], buf_[cur][ni][0], buf_[cur][ni][1]);
        }
      }
    }
    stage  = (stage+1 == NST) ? 0 : stage+1;
    pstage = (pstage+1 == NST) ? 0 : pstage+1;
  }

  #pragma unroll
  for (int mi=0;mi<4;mi++){
    int r1 = m0 + wm + mi*16 + gg;
    int r2 = r1 + 8;
    __half* hp1 = g_h + (size_t)(e*CAPACITY + r1)*DFF + n0;
    __half* hp2 = g_h + (size_t)(e*CAPACITY + r2)*DFF + n0;
    #pragma unroll
    for (int ni=0;ni<4;ni++){
      int col = wn + ni*8 + 2*tg;
      float g0=accG[mi][ni][0], u0=accU[mi][ni][0];
      float g1=accG[mi][ni][1], u1=accU[mi][ni][1];
      float g2=accG[mi][ni][2], u2=accU[mi][ni][2];
      float g3=accG[mi][ni][3], u3=accU[mi][ni][3];
      float h0 = g0*u0/(1.f+__expf(-g0));
      float h1 = g1*u1/(1.f+__expf(-g1));
      float h2 = g2*u2/(1.f+__expf(-g2));
      float h3 = g3*u3/(1.f+__expf(-g3));
      *(__half2*)(hp1 + col) = __floats2half2_rn(h0, h1);
      *(__half2*)(hp2 + col) = __floats2half2_rn(h2, h3);
    }
  }
}

// ---------------- GEMM2: h @ W3^T fp16, BM=128 BN=256 BK=64, frag double-buffer, fused combine ----------------
// grid (20, 4, 8), block 256
__global__ __launch_bounds__(256, 1) void gemm2_kernel(float* __restrict__ out){
  extern __shared__ __align__(16) char sdyn[];

  int e  = blockIdx.z;
  int m0 = blockIdx.x * 128;
  if (m0 >= g_mcount[e]) return;
  int n0 = blockIdx.y * 256;
  int tid = threadIdx.x, w = tid >> 5, lane = tid & 31;

  uint32_t sbase = smem_u32(sdyn);
  int arow = tid >> 3, aseg = tid & 7;

  const __half* srcA = g_h + (size_t)(e*CAPACITY + m0 + arow)*DFF + aseg*8;
  const __half* srcB = g_w3h + ((size_t)e*DMODEL + n0 + arow)*DFF + aseg*8;
  uint32_t dstA0 = (uint32_t)(arow*ROWB + aseg*16);
  uint32_t dstB0 = (uint32_t)(A_B + arow*ROWB + aseg*16);

#define G2_CPA(SB, KOFF) do{ \
  _Pragma("unroll") for (int i=0;i<4;i++) CPA((SB) + dstA0 + i*(32*ROWB), srcA + (size_t)i*(32*DFF) + (KOFF)); \
  _Pragma("unroll") for (int i=0;i<8;i++) CPA((SB) + dstB0 + i*(32*ROWB), srcB + (size_t)i*(32*DFF) + (KOFF)); \
}while(0)

  const int KT = DFF/64;     // 64
  #pragma unroll
  for (int st=0; st<NST-1; st++){
    G2_CPA(sbase + (uint32_t)st*STG_B, st*64);
    CPA_COMMIT();
  }

  int wm = (w>>2)*64, wn = (w&3)*64;
  int gg = lane >> 2, tg = lane & 3;

  uint32_t offA[4];
  #pragma unroll
  for (int mi=0;mi<4;mi++)
    offA[mi] = (uint32_t)((wm + mi*16 + (lane&15))*PADH + (lane>>4)*8)*2u;
  uint32_t offB[4];
  {
    int nrow = wn + ((lane>>4)&1)*8 + (lane&7);
    int kofl = ((lane>>3)&1)*8;
    #pragma unroll
    for (int p=0;p<4;p++)
      offB[p] = (uint32_t)(A_B + ((nrow + p*16)*PADH + kofl)*2);
  }

  float acc[4][8][4];
  #pragma unroll
  for (int a=0;a<4;a++)
    #pragma unroll
    for (int b=0;b<8;b++)
      #pragma unroll
      for (int c=0;c<4;c++) acc[a][b][c]=0.f;

  uint32_t af[2][4][4], bf[2][8][2];

#define G2_LOADF(B, KB) do{ \
  _Pragma("unroll") for (int mi=0;mi<4;mi++) \
    LDSM4(af[B][mi][0],af[B][mi][1],af[B][mi][2],af[B][mi][3], (KB) + offA[mi]); \
  _Pragma("unroll") for (int p=0;p<4;p++) \
    LDSM4(bf[B][2*p][0],bf[B][2*p][1],bf[B][2*p+1][0],bf[B][2*p+1][1], (KB) + offB[p]); \
}while(0)

  int stage = 0, pstage = NST-1;
  for (int kt=0; kt<KT; ++kt){
    CPA_WAIT1();
    __syncthreads();
    if (kt+NST-1 < KT) G2_CPA(sbase + (uint32_t)pstage*STG_B, (kt+NST-1)*64);
    CPA_COMMIT();

    uint32_t sb = sbase + (uint32_t)stage*STG_B;
    G2_LOADF(0, sb);
    #pragma unroll
    for (int kk=0; kk<4; kk++){
      const int cur = kk & 1, nxt = cur ^ 1;
      if (kk < 3) G2_LOADF(nxt, sb + (kk+1)*32);
      #pragma unroll
      for (int ni=0;ni<8;ni++){
        #pragma unroll
        for (int mi=0;mi<4;mi++) mma_f16(acc[mi][ni], af[cur][mi], bf[cur][ni][0], bf[cur][ni][1]);
      }
    }
    stage  = (stage+1 == NST) ? 0 : stage+1;
    pstage = (pstage+1 == NST) ? 0 : pstage+1;
  }

  // epilogue: out[token] += acc * weight (<=2 addends/element -> deterministic)
  #pragma unroll
  for (int mi=0;mi<4;mi++){
    int r1 = m0 + wm + mi*16 + gg;
    int r2 = r1 + 8;
    int t1 = g_rowTok2[e*CAPACITY + r1];
    int t2 = g_rowTok2[e*CAPACITY + r2];
    float w1 = g_rowW[e*CAPACITY + r1];
    float w2 = g_rowW[e*CAPACITY + r2];
    float* op1 = out + (size_t)t1*DMODEL + n0;
    float* op2 = out + (size_t)t2*DMODEL + n0;
    #pragma unroll
    for (int ni=0;ni<8;ni++){
      int col = wn + ni*8 + 2*tg;
      if (t1 >= 0){
        atomicAdd(op1 + col,     acc[mi][ni][0]*w1);
        atomicAdd(op1 + col + 1, acc[mi][ni][1]*w1);
      }
      if (t2 >= 0){
        atomicAdd(op2 + col,     acc[mi][ni][2]*w2);
        atomicAdd(op2 + col + 1, acc[mi][ni][3]*w2);
      }
    }
  }
}

// ---------------- launch ----------------
extern "C" void kernel_launch(void* const* d_in, const int* in_sizes, int n_in,
                              void* d_out, int out_size){
  const float* x     = (const float*)d_in[0];
  const float* gamma = (const float*)d_in[1];
  const float* beta  = (const float*)d_in[2];
  const float* Wr    = (const float*)d_in[3];
  const float* W12   = (const float*)d_in[4];
  const float* W3    = (const float*)d_in[5];
  float* out = (float*)d_out;

  static cudaStream_t s2 = nullptr, s3 = nullptr, s4 = nullptr;
  static cudaEvent_t evF = nullptr, ev12a = nullptr, ev12b = nullptr, ev3 = nullptr, evI = nullptr;
  if (!s2){
    cudaStreamCreateWithFlags(&s2, cudaStreamNonBlocking);
    cudaStreamCreateWithFlags(&s3, cudaStreamNonBlocking);
    cudaStreamCreateWithFlags(&s4, cudaStreamNonBlocking);
    cudaEventCreateWithFlags(&evF, cudaEventDisableTiming);
    cudaEventCreateWithFlags(&ev12a, cudaEventDisableTiming);
    cudaEventCreateWithFlags(&ev12b, cudaEventDisableTiming);
    cudaEventCreateWithFlags(&ev3, cudaEventDisableTiming);
    cudaEventCreateWithFlags(&evI, cudaEventDisableTiming);
    cudaFuncSetAttribute(gemm1_kernel, cudaFuncAttributeMaxDynamicSharedMemorySize, SMEM_BYTES);
    cudaFuncSetAttribute(gemm2_kernel, cudaFuncAttributeMaxDynamicSharedMemorySize, SMEM_BYTES);
  }

  // fork: weight conversions (W12 in two halves) + out-init on side streams
  cudaEventRecord(evF, 0);
  cudaStreamWaitEvent(s2, evF, 0);
  cudaStreamWaitEvent(s3, evF, 0);
  cudaStreamWaitEvent(s4, evF, 0);
  convw12_kernel<<<4096, 256, 0, s2>>>((const float4*)W12, 0);
  cudaEventRecord(ev12a, s2);
  convw12_kernel<<<4096, 256, 0, s2>>>((const float4*)W12, 4);
  cudaEventRecord(ev12b, s2);
  convw3_kernel<<<4096, 256, 0, s3>>>((const float4*)W3);
  cudaEventRecord(ev3, s3);
  init_kernel<<<TTOK, 256, 0, s4>>>((float4*)out);
  cudaEventRecord(evI, s4);

  // main stream: routing chain (hist fused into ln_router; scan fused into rank)
  ln_router_kernel<<<TTOK, 256>>>(x, gamma, beta, Wr);
  cudaStreamWaitEvent(0, evI, 0);
  rank_kernel<<<64, 256>>>();

  // GEMM1 in two halves: first half gated on first conv half (starts earlier)
  cudaStreamWaitEvent(0, ev12a, 0);
  gemm1_kernel<<<dim3(CAPACITY/128, DFF/128, 4), 256, SMEM_BYTES>>>(0);
  cudaStreamWaitEvent(0, ev12b, 0);
  gemm1_kernel<<<dim3(CAPACITY/128, DFF/128, 4), 256, SMEM_BYTES>>>(4);

  cudaStreamWaitEvent(0, ev3, 0);
  gemm2_kernel<<<dim3(CAPACITY/128, DMODEL/256, NEXP), 256, SMEM_BYTES>>>(out);
}

// round 16
// speedup vs baseline: 1.0159x; 1.0159x over previous
#include <cuda_runtime.h>
#include <cuda_fp16.h>
#include <cstdint>

#define TTOK 8192
#define DMODEL 1024
#define DFF 4096
#define NEXP 8
#define CAPACITY 2560
#define NSLOT (TTOK*2)
#define CLAMPV 10000.0f

// GEMM tiling: BM=128, BN=256, BK=64 (halves), 3-stage cp.async
#define PADH 72
#define ROWB 144
#define A_B (128*ROWB)               // 18432
#define B_B (256*ROWB)               // 36864
#define STG_B (A_B+B_B)              // 55296
#define NST 3
#define SMEM_BYTES (NST*STG_B)       // 165888

// ---------------- scratch ----------------
__device__ __half g_xnh[(size_t)TTOK*DMODEL];
__device__ __half g_w12h[(size_t)NEXP*2*DFF*DMODEL];
__device__ __half g_w3h[(size_t)NEXP*DMODEL*DFF];
__device__ __half g_h[(size_t)NEXP*CAPACITY*DFF];
__device__ int   g_slotExpert[NSLOT];
__device__ float g_slotWeight[NSLOT];
__device__ int   g_rowToken[NEXP*CAPACITY];
__device__ int   g_rowTok2[NEXP*CAPACITY];
__device__ float g_rowW[NEXP*CAPACITY];
__device__ int   g_blockHist[64*8];
__device__ int   g_blockBase[64*8];
__device__ int   g_mcount[8];

// ---------------- helpers ----------------
__device__ __forceinline__ uint32_t smem_u32(const void* p){
  uint32_t a; asm("{ .reg .u64 t; cvta.to.shared.u64 t, %1; cvt.u32.u64 %0, t; }" : "=r"(a) : "l"(p));
  return a;
}
__device__ __forceinline__ void mma_f16(float* d, const uint32_t* a, uint32_t b0, uint32_t b1){
  asm volatile("mma.sync.aligned.m16n8k16.row.col.f32.f16.f16.f32 "
    "{%0,%1,%2,%3}, {%4,%5,%6,%7}, {%8,%9}, {%0,%1,%2,%3};\n"
    : "+f"(d[0]),"+f"(d[1]),"+f"(d[2]),"+f"(d[3])
    : "r"(a[0]),"r"(a[1]),"r"(a[2]),"r"(a[3]),"r"(b0),"r"(b1));
}
#define LDSM4(r0,r1,r2,r3,addr) \
  asm volatile("ldmatrix.sync.aligned.m8n8.x4.shared.b16 {%0,%1,%2,%3}, [%4];" \
    : "=r"(r0),"=r"(r1),"=r"(r2),"=r"(r3) : "r"(addr))
#define CPA(dst, src) \
  asm volatile("cp.async.cg.shared.global [%0], [%1], 16;" :: "r"(dst), "l"(src) : "memory")
#define CPA_COMMIT() asm volatile("cp.async.commit_group;" ::: "memory")
#define CPA_WAIT1()  asm volatile("cp.async.wait_group 1;" ::: "memory")

// ---------------- weight conversion ----------------
__global__ __launch_bounds__(256) void convw12_kernel(const float4* __restrict__ w12){
  const size_t N = (size_t)NEXP*2*DFF*DMODEL/8;
  size_t stride = (size_t)gridDim.x*blockDim.x;
  for (size_t i = (size_t)blockIdx.x*blockDim.x + threadIdx.x; i < N; i += stride){
    float4 v0 = w12[i*2], v1 = w12[i*2+1];
    __half2* d = ((__half2*)g_w12h) + i*4;
    d[0] = __floats2half2_rn(v0.x, v0.y);
    d[1] = __floats2half2_rn(v0.z, v0.w);
    d[2] = __floats2half2_rn(v1.x, v1.y);
    d[3] = __floats2half2_rn(v1.z, v1.w);
  }
}
__global__ __launch_bounds__(256) void convw3_kernel(const float4* __restrict__ w3){
  const size_t N = (size_t)NEXP*DMODEL*DFF/8;
  size_t stride = (size_t)gridDim.x*blockDim.x;
  for (size_t i = (size_t)blockIdx.x*blockDim.x + threadIdx.x; i < N; i += stride){
    float4 v0 = w3[i*2], v1 = w3[i*2+1];
    __half2* d = ((__half2*)g_w3h) + i*4;
    d[0] = __floats2half2_rn(v0.x, v0.y);
    d[1] = __floats2half2_rn(v0.z, v0.w);
    d[2] = __floats2half2_rn(v1.x, v1.y);
    d[3] = __floats2half2_rn(v1.z, v1.w);
  }
}

// ---------------- LayerNorm + router + top-2 ----------------
__global__ __launch_bounds__(256) void ln_router_kernel(
    const float* __restrict__ x, const float* __restrict__ gamma,
    const float* __restrict__ beta, const float* __restrict__ Wr)
{
  __shared__ float sx[DMODEL];
  __shared__ float rs[8], rss[8];
  __shared__ float slog[8];
  __shared__ float smu, srstd;
  int t = blockIdx.x, tid = threadIdx.x;
  int w = tid >> 5, lane = tid & 31;

  float4 v = ((const float4*)x)[(size_t)t*256 + tid];
  float s  = v.x+v.y+v.z+v.w;
  float ss = v.x*v.x+v.y*v.y+v.z*v.z+v.w*v.w;
  #pragma unroll
  for (int o=16;o>0;o>>=1){
    s  += __shfl_down_sync(0xffffffffu, s, o);
    ss += __shfl_down_sync(0xffffffffu, ss, o);
  }
  if (lane==0){ rs[w]=s; rss[w]=ss; }
  __syncthreads();
  if (tid==0){
    float S=0.f, SS=0.f;
    #pragma unroll
    for (int i=0;i<8;i++){ S+=rs[i]; SS+=rss[i]; }
    float mu = S * (1.0f/DMODEL);
    float var = SS * (1.0f/DMODEL) - mu*mu;
    smu = mu; srstd = rsqrtf(var + 1e-5f);
  }
  __syncthreads();
  float mu = smu, rstd = srstd;
  float4 gm = ((const float4*)gamma)[tid];
  float4 bt = ((const float4*)beta)[tid];
  float4 xn;
  xn.x = (v.x-mu)*rstd*gm.x + bt.x;
  xn.y = (v.y-mu)*rstd*gm.y + bt.y;
  xn.z = (v.z-mu)*rstd*gm.z + bt.z;
  xn.w = (v.w-mu)*rstd*gm.w + bt.w;
  ((float4*)sx)[tid] = xn;
  __half2 p0 = __floats2half2_rn(xn.x, xn.y);
  __half2 p1 = __floats2half2_rn(xn.z, xn.w);
  __half2* xp = (__half2*)(g_xnh + (size_t)t*DMODEL) + tid*2;
  xp[0]=p0; xp[1]=p1;
  __syncthreads();

  const float* wr = Wr + w*DMODEL;
  float acc = 0.f;
  for (int d=lane; d<DMODEL; d+=32) acc += sx[d]*wr[d];
  #pragma unroll
  for (int o=16;o>0;o>>=1) acc += __shfl_down_sync(0xffffffffu, acc, o);
  if (lane==0) slog[w] = fminf(fmaxf(acc, -CLAMPV), CLAMPV);
  __syncthreads();

  if (tid==0){
    float p[8];
    float m = slog[0];
    #pragma unroll
    for (int e=1;e<8;e++) m = fmaxf(m, slog[e]);
    float den=0.f;
    #pragma unroll
    for (int e=0;e<8;e++){ p[e]=expf(slog[e]-m); den+=p[e]; }
    float inv = 1.f/(den + 1e-12f);
    #pragma unroll
    for (int e=0;e<8;e++) p[e]*=inv;
    int i0=0;
    #pragma unroll
    for (int e=1;e<8;e++) if (p[e]>p[i0]) i0=e;
    int i1 = (i0==0)?1:0;
    #pragma unroll
    for (int e=0;e<8;e++) if (e!=i0 && p[e]>p[i1]) i1=e;
    g_slotExpert[2*t]   = i0; g_slotWeight[2*t]   = p[i0];
    g_slotExpert[2*t+1] = i1; g_slotWeight[2*t+1] = p[i1];
  }
}

// ---------------- routing bookkeeping ----------------
__global__ __launch_bounds__(256) void hist_kernel(){
  __shared__ int h[8];
  if (threadIdx.x < 8) h[threadIdx.x] = 0;
  __syncthreads();
  int e = g_slotExpert[blockIdx.x*256 + threadIdx.x];
  atomicAdd(&h[e], 1);
  __syncthreads();
  if (threadIdx.x < 8) g_blockHist[blockIdx.x*8 + threadIdx.x] = h[threadIdx.x];
}

__global__ __launch_bounds__(256) void scan_kernel(){
  int e = threadIdx.x >> 5, lane = threadIdx.x & 31;
  int b0 = 2*lane, b1 = b0+1;
  int h0 = g_blockHist[b0*8+e], h1 = g_blockHist[b1*8+e];
  int s = h0+h1, incl = s;
  #pragma unroll
  for (int o=1;o<32;o<<=1){
    int n = __shfl_up_sync(0xffffffffu, incl, o);
    if (lane >= o) incl += n;
  }
  int excl = incl - s;
  g_blockBase[b0*8+e] = excl;
  g_blockBase[b1*8+e] = excl + h0;
  if (lane == 31) g_mcount[e] = (incl < CAPACITY) ? incl : CAPACITY;
}

__global__ __launch_bounds__(256) void init_kernel(float4* __restrict__ out){
  int i = blockIdx.x*256 + threadIdx.x;
  out[i] = make_float4(0.f,0.f,0.f,0.f);
  if (i < NEXP*CAPACITY){ g_rowTok2[i] = -1; }
}

// stable rank via match_any + per-warp counts
__global__ __launch_bounds__(256) void rank_kernel(){
  __shared__ int warpCnt[8][8];
  int tid = threadIdx.x, w = tid >> 5, lane = tid & 31;
  if (tid < 64) ((int*)warpCnt)[tid] = 0;
  __syncthreads();
  int s = blockIdx.x*256 + tid;
  int e = g_slotExpert[s];
  unsigned mask = __match_any_sync(0xffffffffu, e);
  int before = __popc(mask & ((1u << lane) - 1u));
  if (lane == (__ffs(mask) - 1)) warpCnt[w][e] = __popc(mask);
  __syncthreads();
  int base = 0;
  #pragma unroll
  for (int ww=0; ww<8; ww++) if (ww < w) base += warpCnt[ww][e];
  int rank = g_blockBase[blockIdx.x*8 + e] + base + before;
  if (rank < CAPACITY){
    int dest = e*CAPACITY + rank;
    g_rowToken[dest] = s >> 1;
    g_rowTok2[dest]  = s >> 1;
    g_rowW[dest]     = g_slotWeight[s];
  }
}

// ---------------- GEMM1: (gathered xn) @ W12^T fp16, BK=64, frag double-buffer, fused SwiGLU ----------------
// grid (20, 32, 8), block 256. tile 128 x (128 g | 128 u)
__global__ __launch_bounds__(256, 1) void gemm1_kernel(){
  extern __shared__ __align__(16) char sdyn[];
  __shared__ int sTok[128];

  int e  = blockIdx.z;
  int m0 = blockIdx.x * 128;
  if (m0 >= g_mcount[e]) return;
  int n0 = blockIdx.y * 128;
  int tid = threadIdx.x, w = tid >> 5, lane = tid & 31;

  if (tid < 128) sTok[tid] = g_rowToken[e*CAPACITY + m0 + tid];
  __syncthreads();

  uint32_t sbase = smem_u32(sdyn);
  int arow = tid >> 3, aseg = tid & 7;

  const __half* srcA[4];
  #pragma unroll
  for (int i=0;i<4;i++) srcA[i] = g_xnh + (size_t)sTok[arow + 32*i]*DMODEL + aseg*8;
  const __half* srcBg = g_w12h + ((size_t)e*2*DFF + n0 + arow)*DMODEL + aseg*8;
  const __half* srcBu = g_w12h + ((size_t)e*2*DFF + DFF + n0 + arow)*DMODEL + aseg*8;
  uint32_t dstA0 = (uint32_t)(arow*ROWB + aseg*16);
  uint32_t dstB0 = (uint32_t)(A_B + arow*ROWB + aseg*16);

#define G1_CPA(SB, KOFF) do{ \
  _Pragma("unroll") for (int i=0;i<4;i++) CPA((SB) + dstA0 + i*(32*ROWB), srcA[i] + (KOFF)); \
  _Pragma("unroll") for (int i=0;i<4;i++) CPA((SB) + dstB0 + i*(32*ROWB), srcBg + i*(32*DMODEL) + (KOFF)); \
  _Pragma("unroll") for (int i=0;i<4;i++) CPA((SB) + dstB0 + (i+4)*(32*ROWB), srcBu + i*(32*DMODEL) + (KOFF)); \
}while(0)

  const int KT = DMODEL/64;      // 16
  #pragma unroll
  for (int st=0; st<NST-1; st++){
    G1_CPA(sbase + (uint32_t)st*STG_B, st*64);
    CPA_COMMIT();
  }

  int wm = (w>>2)*64, wn = (w&3)*32;
  int gg = lane >> 2, tg = lane & 3;

  uint32_t offA[4];
  #pragma unroll
  for (int mi=0;mi<4;mi++)
    offA[mi] = (uint32_t)((wm + mi*16 + (lane&15))*PADH + (lane>>4)*8)*2u;
  uint32_t offBg[2], offBu[2];
  {
    int nrow = wn + ((lane>>4)&1)*8 + (lane&7);
    int kofl = ((lane>>3)&1)*8;
    #pragma unroll
    for (int p=0;p<2;p++){
      offBg[p] = (uint32_t)(A_B + ((nrow + p*16)*PADH + kofl)*2);
      offBu[p] = offBg[p] + (uint32_t)(128*PADH*2);
    }
  }

  float accG[4][4][4], accU[4][4][4];
  #pragma unroll
  for (int a=0;a<4;a++)
    #pragma unroll
    for (int b=0;b<4;b++)
      #pragma unroll
      for (int c=0;c<4;c++){ accG[a][b][c]=0.f; accU[a][b][c]=0.f; }

  uint32_t af[2][4][4], bgf[2][4][2], buf_[2][4][2];

#define G1_LOADF(B, KB) do{ \
  _Pragma("unroll") for (int mi=0;mi<4;mi++) \
    LDSM4(af[B][mi][0],af[B][mi][1],af[B][mi][2],af[B][mi][3], (KB) + offA[mi]); \
  _Pragma("unroll") for (int p=0;p<2;p++){ \
    LDSM4(bgf[B][2*p][0],bgf[B][2*p][1],bgf[B][2*p+1][0],bgf[B][2*p+1][1], (KB) + offBg[p]); \
    LDSM4(buf_[B][2*p][0],buf_[B][2*p][1],buf_[B][2*p+1][0],buf_[B][2*p+1][1], (KB) + offBu[p]); \
  } \
}while(0)

  int stage = 0, pstage = NST-1;
  for (int kt=0; kt<KT; ++kt){
    CPA_WAIT1();
    __syncthreads();
    if (kt+NST-1 < KT) G1_CPA(sbase + (uint32_t)pstage*STG_B, (kt+NST-1)*64);
    CPA_COMMIT();

    uint32_t sb = sbase + (uint32_t)stage*STG_B;
    G1_LOADF(0, sb);
    #pragma unroll
    for (int kk=0; kk<4; kk++){
      const int cur = kk & 1, nxt = cur ^ 1;
      if (kk < 3) G1_LOADF(nxt, sb + (kk+1)*32);
      #pragma unroll
      for (int ni=0;ni<4;ni++){
        #pragma unroll
        for (int mi=0;mi<4;mi++){
          mma_f16(accG[mi][ni], af[cur][mi], bgf[cur][ni][0], bgf[cur][ni][1]);
          mma_f16(accU[mi][ni], af[cur][mi], buf_[cur][ni][0], buf_[cur][ni][1]);
        }
      }
    }
    stage  = (stage+1 == NST) ? 0 : stage+1;
    pstage = (pstage+1 == NST) ? 0 : pstage+1;
  }

  #pragma unroll
  for (int mi=0;mi<4;mi++){
    int r1 = m0 + wm + mi*16 + gg;
    int r2 = r1 + 8;
    __half* hp1 = g_h + (size_t)(e*CAPACITY + r1)*DFF + n0;
    __half* hp2 = g_h + (size_t)(e*CAPACITY + r2)*DFF + n0;
    #pragma unroll
    for (int ni=0;ni<4;ni++){
      int col = wn + ni*8 + 2*tg;
      float g0=accG[mi][ni][0], u0=accU[mi][ni][0];
      float g1=accG[mi][ni][1], u1=accU[mi][ni][1];
      float g2=accG[mi][ni][2], u2=accU[mi][ni][2];
      float g3=accG[mi][ni][3], u3=accU[mi][ni][3];
      float h0 = g0*u0/(1.f+__expf(-g0));
      float h1 = g1*u1/(1.f+__expf(-g1));
      float h2 = g2*u2/(1.f+__expf(-g2));
      float h3 = g3*u3/(1.f+__expf(-g3));
      *(__half2*)(hp1 + col) = __floats2half2_rn(h0, h1);
      *(__half2*)(hp2 + col) = __floats2half2_rn(h2, h3);
    }
  }
}

// ---------------- GEMM2: h @ W3^T fp16, BM=128 BN=256 BK=64, frag double-buffer, fused combine ----------------
// grid (20, 4, 8), block 256
__global__ __launch_bounds__(256, 1) void gemm2_kernel(float* __restrict__ out){
  extern __shared__ __align__(16) char sdyn[];

  int e  = blockIdx.z;
  int m0 = blockIdx.x * 128;
  if (m0 >= g_mcount[e]) return;
  int n0 = blockIdx.y * 256;
  int tid = threadIdx.x, w = tid >> 5, lane = tid & 31;

  uint32_t sbase = smem_u32(sdyn);
  int arow = tid >> 3, aseg = tid & 7;

  const __half* srcA = g_h + (size_t)(e*CAPACITY + m0 + arow)*DFF + aseg*8;
  const __half* srcB = g_w3h + ((size_t)e*DMODEL + n0 + arow)*DFF + aseg*8;
  uint32_t dstA0 = (uint32_t)(arow*ROWB + aseg*16);
  uint32_t dstB0 = (uint32_t)(A_B + arow*ROWB + aseg*16);

#define G2_CPA(SB, KOFF) do{ \
  _Pragma("unroll") for (int i=0;i<4;i++) CPA((SB) + dstA0 + i*(32*ROWB), srcA + (size_t)i*(32*DFF) + (KOFF)); \
  _Pragma("unroll") for (int i=0;i<8;i++) CPA((SB) + dstB0 + i*(32*ROWB), srcB + (size_t)i*(32*DFF) + (KOFF)); \
}while(0)

  const int KT = DFF/64;     // 64
  #pragma unroll
  for (int st=0; st<NST-1; st++){
    G2_CPA(sbase + (uint32_t)st*STG_B, st*64);
    CPA_COMMIT();
  }

  int wm = (w>>2)*64, wn = (w&3)*64;
  int gg = lane >> 2, tg = lane & 3;

  uint32_t offA[4];
  #pragma unroll
  for (int mi=0;mi<4;mi++)
    offA[mi] = (uint32_t)((wm + mi*16 + (lane&15))*PADH + (lane>>4)*8)*2u;
  uint32_t offB[4];
  {
    int nrow = wn + ((lane>>4)&1)*8 + (lane&7);
    int kofl = ((lane>>3)&1)*8;
    #pragma unroll
    for (int p=0;p<4;p++)
      offB[p] = (uint32_t)(A_B + ((nrow + p*16)*PADH + kofl)*2);
  }

  float acc[4][8][4];
  #pragma unroll
  for (int a=0;a<4;a++)
    #pragma unroll
    for (int b=0;b<8;b++)
      #pragma unroll
      for (int c=0;c<4;c++) acc[a][b][c]=0.f;

  uint32_t af[2][4][4], bf[2][8][2];

#define G2_LOADF(B, KB) do{ \
  _Pragma("unroll") for (int mi=0;mi<4;mi++) \
    LDSM4(af[B][mi][0],af[B][mi][1],af[B][mi][2],af[B][mi][3], (KB) + offA[mi]); \
  _Pragma("unroll") for (int p=0;p<4;p++) \
    LDSM4(bf[B][2*p][0],bf[B][2*p][1],bf[B][2*p+1][0],bf[B][2*p+1][1], (KB) + offB[p]); \
}while(0)

  int stage = 0, pstage = NST-1;
  for (int kt=0; kt<KT; ++kt){
    CPA_WAIT1();
    __syncthreads();
    if (kt+NST-1 < KT) G2_CPA(sbase + (uint32_t)pstage*STG_B, (kt+NST-1)*64);
    CPA_COMMIT();

    uint32_t sb = sbase + (uint32_t)stage*STG_B;
    G2_LOADF(0, sb);
    #pragma unroll
    for (int kk=0; kk<4; kk++){
      const int cur = kk & 1, nxt = cur ^ 1;
      if (kk < 3) G2_LOADF(nxt, sb + (kk+1)*32);
      #pragma unroll
      for (int ni=0;ni<8;ni++){
        #pragma unroll
        for (int mi=0;mi<4;mi++) mma_f16(acc[mi][ni], af[cur][mi], bf[cur][ni][0], bf[cur][ni][1]);
      }
    }
    stage  = (stage+1 == NST) ? 0 : stage+1;
    pstage = (pstage+1 == NST) ? 0 : pstage+1;
  }

  // epilogue: out[token] += acc * weight (<=2 addends/element -> deterministic)
  #pragma unroll
  for (int mi=0;mi<4;mi++){
    int r1 = m0 + wm + mi*16 + gg;
    int r2 = r1 + 8;
    int t1 = g_rowTok2[e*CAPACITY + r1];
    int t2 = g_rowTok2[e*CAPACITY + r2];
    float w1 = g_rowW[e*CAPACITY + r1];
    float w2 = g_rowW[e*CAPACITY + r2];
    float* op1 = out + (size_t)t1*DMODEL + n0;
    float* op2 = out + (size_t)t2*DMODEL + n0;
    #pragma unroll
    for (int ni=0;ni<8;ni++){
      int col = wn + ni*8 + 2*tg;
      if (t1 >= 0){
        atomicAdd(op1 + col,     acc[mi][ni][0]*w1);
        atomicAdd(op1 + col + 1, acc[mi][ni][1]*w1);
      }
      if (t2 >= 0){
        atomicAdd(op2 + col,     acc[mi][ni][2]*w2);
        atomicAdd(op2 + col + 1, acc[mi][ni][3]*w2);
      }
    }
  }
}

// ---------------- launch ----------------
extern "C" void kernel_launch(void* const* d_in, const int* in_sizes, int n_in,
                              void* d_out, int out_size){
  const float* x     = (const float*)d_in[0];
  const float* gamma = (const float*)d_in[1];
  const float* beta  = (const float*)d_in[2];
  const float* Wr    = (const float*)d_in[3];
  const float* W12   = (const float*)d_in[4];
  const float* W3    = (const float*)d_in[5];
  float* out = (float*)d_out;

  static cudaStream_t s2 = nullptr, s3 = nullptr, s4 = nullptr;
  static cudaEvent_t evF = nullptr, ev12 = nullptr, ev3 = nullptr, evI = nullptr;
  if (!s2){
    cudaStreamCreateWithFlags(&s2, cudaStreamNonBlocking);
    cudaStreamCreateWithFlags(&s3, cudaStreamNonBlocking);
    cudaStreamCreateWithFlags(&s4, cudaStreamNonBlocking);
    cudaEventCreateWithFlags(&evF, cudaEventDisableTiming);
    cudaEventCreateWithFlags(&ev12, cudaEventDisableTiming);
    cudaEventCreateWithFlags(&ev3, cudaEventDisableTiming);
    cudaEventCreateWithFlags(&evI, cudaEventDisableTiming);
    cudaFuncSetAttribute(gemm1_kernel, cudaFuncAttributeMaxDynamicSharedMemorySize, SMEM_BYTES);
    cudaFuncSetAttribute(gemm2_kernel, cudaFuncAttributeMaxDynamicSharedMemorySize, SMEM_BYTES);
  }

  // fork: weight conversions + out-init on side streams
  cudaEventRecord(evF, 0);
  cudaStreamWaitEvent(s2, evF, 0);
  cudaStreamWaitEvent(s3, evF, 0);
  cudaStreamWaitEvent(s4, evF, 0);
  convw12_kernel<<<8192, 256, 0, s2>>>((const float4*)W12);
  cudaEventRecord(ev12, s2);
  convw3_kernel<<<4096, 256, 0, s3>>>((const float4*)W3);
  cudaEventRecord(ev3, s3);
  init_kernel<<<TTOK, 256, 0, s4>>>((float4*)out);
  cudaEventRecord(evI, s4);

  // main stream: routing chain
  ln_router_kernel<<<TTOK, 256>>>(x, gamma, beta, Wr);
  hist_kernel<<<64, 256>>>();
  scan_kernel<<<1, 256>>>();
  cudaStreamWaitEvent(0, evI, 0);
  rank_kernel<<<64, 256>>>();

  // join W12 before GEMM1; W3 joins before GEMM2 (overlaps GEMM1)
  cudaStreamWaitEvent(0, ev12, 0);
  gemm1_kernel<<<dim3(CAPACITY/128, DFF/128, NEXP), 256, SMEM_BYTES>>>();
  cudaStreamWaitEvent(0, ev3, 0);
  gemm2_kernel<<<dim3(CAPACITY/128, DMODEL/256, NEXP), 256, SMEM_BYTES>>>(out);
}

// round 17
// speedup vs baseline: 1.0252x; 1.0092x over previous
#include <cuda_runtime.h>
#include <cuda_fp16.h>
#include <cstdint>

#define TTOK 8192
#define DMODEL 1024
#define DFF 4096
#define NEXP 8
#define CAPACITY 2560
#define NSLOT (TTOK*2)
#define CLAMPV 10000.0f

// GEMM tiling: BM=128, BN=256, BK=64 (halves), 3-stage cp.async
#define PADH 72
#define ROWB 144
#define A_B (128*ROWB)               // 18432
#define B_B (256*ROWB)               // 36864
#define STG_B (A_B+B_B)              // 55296
#define NST 3
#define SMEM_BYTES (NST*STG_B)       // 165888

// ---------------- scratch ----------------
__device__ __half g_xnh[(size_t)TTOK*DMODEL];
__device__ __half g_w12h[(size_t)NEXP*2*DFF*DMODEL];
__device__ __half g_w3h[(size_t)NEXP*DMODEL*DFF];
__device__ __half g_h[(size_t)NEXP*CAPACITY*DFF];
__device__ int   g_slotExpert[NSLOT];
__device__ float g_slotWeight[NSLOT];
__device__ int   g_rowToken[NEXP*CAPACITY];
__device__ int   g_rowTok2[NEXP*CAPACITY];
__device__ float g_rowW[NEXP*CAPACITY];
__device__ int   g_blockHist[64*8];
__device__ int   g_blockBase[64*8];
__device__ int   g_mcount[8];

// ---------------- helpers ----------------
__device__ __forceinline__ uint32_t smem_u32(const void* p){
  uint32_t a; asm("{ .reg .u64 t; cvta.to.shared.u64 t, %1; cvt.u32.u64 %0, t; }" : "=r"(a) : "l"(p));
  return a;
}
__device__ __forceinline__ void mma_f16(float* d, const uint32_t* a, uint32_t b0, uint32_t b1){
  asm volatile("mma.sync.aligned.m16n8k16.row.col.f32.f16.f16.f32 "
    "{%0,%1,%2,%3}, {%4,%5,%6,%7}, {%8,%9}, {%0,%1,%2,%3};\n"
    : "+f"(d[0]),"+f"(d[1]),"+f"(d[2]),"+f"(d[3])
    : "r"(a[0]),"r"(a[1]),"r"(a[2]),"r"(a[3]),"r"(b0),"r"(b1));
}
#define LDSM4(r0,r1,r2,r3,addr) \
  asm volatile("ldmatrix.sync.aligned.m8n8.x4.shared.b16 {%0,%1,%2,%3}, [%4];" \
    : "=r"(r0),"=r"(r1),"=r"(r2),"=r"(r3) : "r"(addr))
#define CPA(dst, src) \
  asm volatile("cp.async.cg.shared.global [%0], [%1], 16;" :: "r"(dst), "l"(src) : "memory")
#define CPA_COMMIT() asm volatile("cp.async.commit_group;" ::: "memory")
#define CPA_WAIT1()  asm volatile("cp.async.wait_group 1;" ::: "memory")

// ---------------- weight conversion ----------------
__global__ __launch_bounds__(256) void convw12_kernel(const float4* __restrict__ w12){
  const size_t N = (size_t)NEXP*2*DFF*DMODEL/8;
  size_t stride = (size_t)gridDim.x*blockDim.x;
  for (size_t i = (size_t)blockIdx.x*blockDim.x + threadIdx.x; i < N; i += stride){
    float4 v0 = w12[i*2], v1 = w12[i*2+1];
    __half2* d = ((__half2*)g_w12h) + i*4;
    d[0] = __floats2half2_rn(v0.x, v0.y);
    d[1] = __floats2half2_rn(v0.z, v0.w);
    d[2] = __floats2half2_rn(v1.x, v1.y);
    d[3] = __floats2half2_rn(v1.z, v1.w);
  }
}
__global__ __launch_bounds__(256) void convw3_kernel(const float4* __restrict__ w3){
  const size_t N = (size_t)NEXP*DMODEL*DFF/8;
  size_t stride = (size_t)gridDim.x*blockDim.x;
  for (size_t i = (size_t)blockIdx.x*blockDim.x + threadIdx.x; i < N; i += stride){
    float4 v0 = w3[i*2], v1 = w3[i*2+1];
    __half2* d = ((__half2*)g_w3h) + i*4;
    d[0] = __floats2half2_rn(v0.x, v0.y);
    d[1] = __floats2half2_rn(v0.z, v0.w);
    d[2] = __floats2half2_rn(v1.x, v1.y);
    d[3] = __floats2half2_rn(v1.z, v1.w);
  }
}

// ---------------- LayerNorm + router + top-2 ----------------
__global__ __launch_bounds__(256) void ln_router_kernel(
    const float* __restrict__ x, const float* __restrict__ gamma,
    const float* __restrict__ beta, const float* __restrict__ Wr)
{
  __shared__ float sx[DMODEL];
  __shared__ float rs[8], rss[8];
  __shared__ float slog[8];
  __shared__ float smu, srstd;
  int t = blockIdx.x, tid = threadIdx.x;
  int w = tid >> 5, lane = tid & 31;

  float4 v = ((const float4*)x)[(size_t)t*256 + tid];
  float s  = v.x+v.y+v.z+v.w;
  float ss = v.x*v.x+v.y*v.y+v.z*v.z+v.w*v.w;
  #pragma unroll
  for (int o=16;o>0;o>>=1){
    s  += __shfl_down_sync(0xffffffffu, s, o);
    ss += __shfl_down_sync(0xffffffffu, ss, o);
  }
  if (lane==0){ rs[w]=s; rss[w]=ss; }
  __syncthreads();
  if (tid==0){
    float S=0.f, SS=0.f;
    #pragma unroll
    for (int i=0;i<8;i++){ S+=rs[i]; SS+=rss[i]; }
    float mu = S * (1.0f/DMODEL);
    float var = SS * (1.0f/DMODEL) - mu*mu;
    smu = mu; srstd = rsqrtf(var + 1e-5f);
  }
  __syncthreads();
  float mu = smu, rstd = srstd;
  float4 gm = ((const float4*)gamma)[tid];
  float4 bt = ((const float4*)beta)[tid];
  float4 xn;
  xn.x = (v.x-mu)*rstd*gm.x + bt.x;
  xn.y = (v.y-mu)*rstd*gm.y + bt.y;
  xn.z = (v.z-mu)*rstd*gm.z + bt.z;
  xn.w = (v.w-mu)*rstd*gm.w + bt.w;
  ((float4*)sx)[tid] = xn;
  __half2 p0 = __floats2half2_rn(xn.x, xn.y);
  __half2 p1 = __floats2half2_rn(xn.z, xn.w);
  __half2* xp = (__half2*)(g_xnh + (size_t)t*DMODEL) + tid*2;
  xp[0]=p0; xp[1]=p1;
  __syncthreads();

  const float* wr = Wr + w*DMODEL;
  float acc = 0.f;
  for (int d=lane; d<DMODEL; d+=32) acc += sx[d]*wr[d];
  #pragma unroll
  for (int o=16;o>0;o>>=1) acc += __shfl_down_sync(0xffffffffu, acc, o);
  if (lane==0) slog[w] = fminf(fmaxf(acc, -CLAMPV), CLAMPV);
  __syncthreads();

  if (tid==0){
    float p[8];
    float m = slog[0];
    #pragma unroll
    for (int e=1;e<8;e++) m = fmaxf(m, slog[e]);
    float den=0.f;
    #pragma unroll
    for (int e=0;e<8;e++){ p[e]=expf(slog[e]-m); den+=p[e]; }
    float inv = 1.f/(den + 1e-12f);
    #pragma unroll
    for (int e=0;e<8;e++) p[e]*=inv;
    int i0=0;
    #pragma unroll
    for (int e=1;e<8;e++) if (p[e]>p[i0]) i0=e;
    int i1 = (i0==0)?1:0;
    #pragma unroll
    for (int e=0;e<8;e++) if (e!=i0 && p[e]>p[i1]) i1=e;
    g_slotExpert[2*t]   = i0; g_slotWeight[2*t]   = p[i0];
    g_slotExpert[2*t+1] = i1; g_slotWeight[2*t+1] = p[i1];
  }
}

// ---------------- routing bookkeeping ----------------
__global__ __launch_bounds__(256) void hist_kernel(){
  __shared__ int h[8];
  if (threadIdx.x < 8) h[threadIdx.x] = 0;
  __syncthreads();
  int e = g_slotExpert[blockIdx.x*256 + threadIdx.x];
  atomicAdd(&h[e], 1);
  __syncthreads();
  if (threadIdx.x < 8) g_blockHist[blockIdx.x*8 + threadIdx.x] = h[threadIdx.x];
}

__global__ __launch_bounds__(256) void scan_kernel(){
  int e = threadIdx.x >> 5, lane = threadIdx.x & 31;
  int b0 = 2*lane, b1 = b0+1;
  int h0 = g_blockHist[b0*8+e], h1 = g_blockHist[b1*8+e];
  int s = h0+h1, incl = s;
  #pragma unroll
  for (int o=1;o<32;o<<=1){
    int n = __shfl_up_sync(0xffffffffu, incl, o);
    if (lane >= o) incl += n;
  }
  int excl = incl - s;
  g_blockBase[b0*8+e] = excl;
  g_blockBase[b1*8+e] = excl + h0;
  if (lane == 31) g_mcount[e] = (incl < CAPACITY) ? incl : CAPACITY;
}

__global__ __launch_bounds__(256) void init_kernel(float4* __restrict__ out){
  int i = blockIdx.x*256 + threadIdx.x;
  out[i] = make_float4(0.f,0.f,0.f,0.f);
  if (i < NEXP*CAPACITY){ g_rowTok2[i] = -1; }
}

// stable rank via match_any + per-warp counts
__global__ __launch_bounds__(256) void rank_kernel(){
  __shared__ int warpCnt[8][8];
  int tid = threadIdx.x, w = tid >> 5, lane = tid & 31;
  if (tid < 64) ((int*)warpCnt)[tid] = 0;
  __syncthreads();
  int s = blockIdx.x*256 + tid;
  int e = g_slotExpert[s];
  unsigned mask = __match_any_sync(0xffffffffu, e);
  int before = __popc(mask & ((1u << lane) - 1u));
  if (lane == (__ffs(mask) - 1)) warpCnt[w][e] = __popc(mask);
  __syncthreads();
  int base = 0;
  #pragma unroll
  for (int ww=0; ww<8; ww++) if (ww < w) base += warpCnt[ww][e];
  int rank = g_blockBase[blockIdx.x*8 + e] + base + before;
  if (rank < CAPACITY){
    int dest = e*CAPACITY + rank;
    g_rowToken[dest] = s >> 1;
    g_rowTok2[dest]  = s >> 1;
    g_rowW[dest]     = g_slotWeight[s];
  }
}

// ---------------- GEMM1 (4-expert group): (gathered xn) @ W12^T fp16, fused SwiGLU ----------------
// grid (20, 32, 4), block 256. tile 128 x (128 g | 128 u)
__global__ __launch_bounds__(256, 1) void gemm1_kernel(int e0){
  extern __shared__ __align__(16) char sdyn[];
  __shared__ int sTok[128];

  int e  = e0 + blockIdx.z;
  int m0 = blockIdx.x * 128;
  if (m0 >= g_mcount[e]) return;
  int n0 = blockIdx.y * 128;
  int tid = threadIdx.x, w = tid >> 5, lane = tid & 31;

  if (tid < 128) sTok[tid] = g_rowToken[e*CAPACITY + m0 + tid];
  __syncthreads();

  uint32_t sbase = smem_u32(sdyn);
  int arow = tid >> 3, aseg = tid & 7;

  const __half* srcA[4];
  #pragma unroll
  for (int i=0;i<4;i++) srcA[i] = g_xnh + (size_t)sTok[arow + 32*i]*DMODEL + aseg*8;
  const __half* srcBg = g_w12h + ((size_t)e*2*DFF + n0 + arow)*DMODEL + aseg*8;
  const __half* srcBu = g_w12h + ((size_t)e*2*DFF + DFF + n0 + arow)*DMODEL + aseg*8;
  uint32_t dstA0 = (uint32_t)(arow*ROWB + aseg*16);
  uint32_t dstB0 = (uint32_t)(A_B + arow*ROWB + aseg*16);

#define G1_CPA(SB, KOFF) do{ \
  _Pragma("unroll") for (int i=0;i<4;i++) CPA((SB) + dstA0 + i*(32*ROWB), srcA[i] + (KOFF)); \
  _Pragma("unroll") for (int i=0;i<4;i++) CPA((SB) + dstB0 + i*(32*ROWB), srcBg + i*(32*DMODEL) + (KOFF)); \
  _Pragma("unroll") for (int i=0;i<4;i++) CPA((SB) + dstB0 + (i+4)*(32*ROWB), srcBu + i*(32*DMODEL) + (KOFF)); \
}while(0)

  const int KT = DMODEL/64;      // 16
  #pragma unroll
  for (int st=0; st<NST-1; st++){
    G1_CPA(sbase + (uint32_t)st*STG_B, st*64);
    CPA_COMMIT();
  }

  int wm = (w>>2)*64, wn = (w&3)*32;
  int gg = lane >> 2, tg = lane & 3;

  uint32_t offA[4];
  #pragma unroll
  for (int mi=0;mi<4;mi++)
    offA[mi] = (uint32_t)((wm + mi*16 + (lane&15))*PADH + (lane>>4)*8)*2u;
  uint32_t offBg[2], offBu[2];
  {
    int nrow = wn + ((lane>>4)&1)*8 + (lane&7);
    int kofl = ((lane>>3)&1)*8;
    #pragma unroll
    for (int p=0;p<2;p++){
      offBg[p] = (uint32_t)(A_B + ((nrow + p*16)*PADH + kofl)*2);
      offBu[p] = offBg[p] + (uint32_t)(128*PADH*2);
    }
  }

  float accG[4][4][4], accU[4][4][4];
  #pragma unroll
  for (int a=0;a<4;a++)
    #pragma unroll
    for (int b=0;b<4;b++)
      #pragma unroll
      for (int c=0;c<4;c++){ accG[a][b][c]=0.f; accU[a][b][c]=0.f; }

  uint32_t af[2][4][4], bgf[2][4][2], buf_[2][4][2];

#define G1_LOADF(B, KB) do{ \
  _Pragma("unroll") for (int mi=0;mi<4;mi++) \
    LDSM4(af[B][mi][0],af[B][mi][1],af[B][mi][2],af[B][mi][3], (KB) + offA[mi]); \
  _Pragma("unroll") for (int p=0;p<2;p++){ \
    LDSM4(bgf[B][2*p][0],bgf[B][2*p][1],bgf[B][2*p+1][0],bgf[B][2*p+1][1], (KB) + offBg[p]); \
    LDSM4(buf_[B][2*p][0],buf_[B][2*p][1],buf_[B][2*p+1][0],buf_[B][2*p+1][1], (KB) + offBu[p]); \
  } \
}while(0)

  int stage = 0, pstage = NST-1;
  for (int kt=0; kt<KT; ++kt){
    CPA_WAIT1();
    __syncthreads();
    if (kt+NST-1 < KT) G1_CPA(sbase + (uint32_t)pstage*STG_B, (kt+NST-1)*64);
    CPA_COMMIT();

    uint32_t sb = sbase + (uint32_t)stage*STG_B;
    G1_LOADF(0, sb);
    #pragma unroll
    for (int kk=0; kk<4; kk++){
      const int cur = kk & 1, nxt = cur ^ 1;
      if (kk < 3) G1_LOADF(nxt, sb + (kk+1)*32);
      #pragma unroll
      for (int ni=0;ni<4;ni++){
        #pragma unroll
        for (int mi=0;mi<4;mi++){
          mma_f16(accG[mi][ni], af[cur][mi], bgf[cur][ni][0], bgf[cur][ni][1]);
          mma_f16(accU[mi][ni], af[cur][mi], buf_[cur][ni][0], buf_[cur][ni][1]);
        }
      }
    }
    stage  = (stage+1 == NST) ? 0 : stage+1;
    pstage = (pstage+1 == NST) ? 0 : pstage+1;
  }

  #pragma unroll
  for (int mi=0;mi<4;mi++){
    int r1 = m0 + wm + mi*16 + gg;
    int r2 = r1 + 8;
    __half* hp1 = g_h + (size_t)(e*CAPACITY + r1)*DFF + n0;
    __half* hp2 = g_h + (size_t)(e*CAPACITY + r2)*DFF + n0;
    #pragma unroll
    for (int ni=0;ni<4;ni++){
      int col = wn + ni*8 + 2*tg;
      float g0=accG[mi][ni][0], u0=accU[mi][ni][0];
      float g1=accG[mi][ni][1], u1=accU[mi][ni][1];
      float g2=accG[mi][ni][2], u2=accU[mi][ni][2];
      float g3=accG[mi][ni][3], u3=accU[mi][ni][3];
      float h0 = g0*u0/(1.f+__expf(-g0));
      float h1 = g1*u1/(1.f+__expf(-g1));
      float h2 = g2*u2/(1.f+__expf(-g2));
      float h3 = g3*u3/(1.f+__expf(-g3));
      *(__half2*)(hp1 + col) = __floats2half2_rn(h0, h1);
      *(__half2*)(hp2 + col) = __floats2half2_rn(h2, h3);
    }
  }
}

// ---------------- GEMM2 (4-expert group): h @ W3^T fp16, fused weighted atomic combine ----------------
// grid (20, 4, 4), block 256. tile 128 x 256
__global__ __launch_bounds__(256, 1) void gemm2_kernel(float* __restrict__ out, int e0){
  extern __shared__ __align__(16) char sdyn[];

  int e  = e0 + blockIdx.z;
  int m0 = blockIdx.x * 128;
  if (m0 >= g_mcount[e]) return;
  int n0 = blockIdx.y * 256;
  int tid = threadIdx.x, w = tid >> 5, lane = tid & 31;

  uint32_t sbase = smem_u32(sdyn);
  int arow = tid >> 3, aseg = tid & 7;

  const __half* srcA = g_h + (size_t)(e*CAPACITY + m0 + arow)*DFF + aseg*8;
  const __half* srcB = g_w3h + ((size_t)e*DMODEL + n0 + arow)*DFF + aseg*8;
  uint32_t dstA0 = (uint32_t)(arow*ROWB + aseg*16);
  uint32_t dstB0 = (uint32_t)(A_B + arow*ROWB + aseg*16);

#define G2_CPA(SB, KOFF) do{ \
  _Pragma("unroll") for (int i=0;i<4;i++) CPA((SB) + dstA0 + i*(32*ROWB), srcA + (size_t)i*(32*DFF) + (KOFF)); \
  _Pragma("unroll") for (int i=0;i<8;i++) CPA((SB) + dstB0 + i*(32*ROWB), srcB + (size_t)i*(32*DFF) + (KOFF)); \
}while(0)

  const int KT = DFF/64;     // 64
  #pragma unroll
  for (int st=0; st<NST-1; st++){
    G2_CPA(sbase + (uint32_t)st*STG_B, st*64);
    CPA_COMMIT();
  }

  int wm = (w>>2)*64, wn = (w&3)*64;
  int gg = lane >> 2, tg = lane & 3;

  uint32_t offA[4];
  #pragma unroll
  for (int mi=0;mi<4;mi++)
    offA[mi] = (uint32_t)((wm + mi*16 + (lane&15))*PADH + (lane>>4)*8)*2u;
  uint32_t offB[4];
  {
    int nrow = wn + ((lane>>4)&1)*8 + (lane&7);
    int kofl = ((lane>>3)&1)*8;
    #pragma unroll
    for (int p=0;p<4;p++)
      offB[p] = (uint32_t)(A_B + ((nrow + p*16)*PADH + kofl)*2);
  }

  float acc[4][8][4];
  #pragma unroll
  for (int a=0;a<4;a++)
    #pragma unroll
    for (int b=0;b<8;b++)
      #pragma unroll
      for (int c=0;c<4;c++) acc[a][b][c]=0.f;

  uint32_t af[2][4][4], bf[2][8][2];

#define G2_LOADF(B, KB) do{ \
  _Pragma("unroll") for (int mi=0;mi<4;mi++) \
    LDSM4(af[B][mi][0],af[B][mi][1],af[B][mi][2],af[B][mi][3], (KB) + offA[mi]); \
  _Pragma("unroll") for (int p=0;p<4;p++) \
    LDSM4(bf[B][2*p][0],bf[B][2*p][1],bf[B][2*p+1][0],bf[B][2*p+1][1], (KB) + offB[p]); \
}while(0)

  int stage = 0, pstage = NST-1;
  for (int kt=0; kt<KT; ++kt){
    CPA_WAIT1();
    __syncthreads();
    if (kt+NST-1 < KT) G2_CPA(sbase + (uint32_t)pstage*STG_B, (kt+NST-1)*64);
    CPA_COMMIT();

    uint32_t sb = sbase + (uint32_t)stage*STG_B;
    G2_LOADF(0, sb);
    #pragma unroll
    for (int kk=0; kk<4; kk++){
      const int cur = kk & 1, nxt = cur ^ 1;
      if (kk < 3) G2_LOADF(nxt, sb + (kk+1)*32);
      #pragma unroll
      for (int ni=0;ni<8;ni++){
        #pragma unroll
        for (int mi=0;mi<4;mi++) mma_f16(acc[mi][ni], af[cur][mi], bf[cur][ni][0], bf[cur][ni][1]);
      }
    }
    stage  = (stage+1 == NST) ? 0 : stage+1;
    pstage = (pstage+1 == NST) ? 0 : pstage+1;
  }

  // epilogue: out[token] += acc * weight (<=2 addends/element -> deterministic)
  #pragma unroll
  for (int mi=0;mi<4;mi++){
    int r1 = m0 + wm + mi*16 + gg;
    int r2 = r1 + 8;
    int t1 = g_rowTok2[e*CAPACITY + r1];
    int t2 = g_rowTok2[e*CAPACITY + r2];
    float w1 = g_rowW[e*CAPACITY + r1];
    float w2 = g_rowW[e*CAPACITY + r2];
    float* op1 = out + (size_t)t1*DMODEL + n0;
    float* op2 = out + (size_t)t2*DMODEL + n0;
    #pragma unroll
    for (int ni=0;ni<8;ni++){
      int col = wn + ni*8 + 2*tg;
      if (t1 >= 0){
        atomicAdd(op1 + col,     acc[mi][ni][0]*w1);
        atomicAdd(op1 + col + 1, acc[mi][ni][1]*w1);
      }
      if (t2 >= 0){
        atomicAdd(op2 + col,     acc[mi][ni][2]*w2);
        atomicAdd(op2 + col + 1, acc[mi][ni][3]*w2);
      }
    }
  }
}

// ---------------- launch ----------------
extern "C" void kernel_launch(void* const* d_in, const int* in_sizes, int n_in,
                              void* d_out, int out_size){
  const float* x     = (const float*)d_in[0];
  const float* gamma = (const float*)d_in[1];
  const float* beta  = (const float*)d_in[2];
  const float* Wr    = (const float*)d_in[3];
  const float* W12   = (const float*)d_in[4];
  const float* W3    = (const float*)d_in[5];
  float* out = (float*)d_out;

  static cudaStream_t s2 = nullptr, s3 = nullptr, s4 = nullptr;
  static cudaEvent_t evF = nullptr, ev12 = nullptr, ev3 = nullptr, evI = nullptr;
  static cudaEvent_t evR = nullptr, evG2b = nullptr;
  if (!s2){
    cudaStreamCreateWithFlags(&s2, cudaStreamNonBlocking);
    cudaStreamCreateWithFlags(&s3, cudaStreamNonBlocking);
    cudaStreamCreateWithFlags(&s4, cudaStreamNonBlocking);
    cudaEventCreateWithFlags(&evF, cudaEventDisableTiming);
    cudaEventCreateWithFlags(&ev12, cudaEventDisableTiming);
    cudaEventCreateWithFlags(&ev3, cudaEventDisableTiming);
    cudaEventCreateWithFlags(&evI, cudaEventDisableTiming);
    cudaEventCreateWithFlags(&evR, cudaEventDisableTiming);
    cudaEventCreateWithFlags(&evG2b, cudaEventDisableTiming);
    cudaFuncSetAttribute(gemm1_kernel, cudaFuncAttributeMaxDynamicSharedMemorySize, SMEM_BYTES);
    cudaFuncSetAttribute(gemm2_kernel, cudaFuncAttributeMaxDynamicSharedMemorySize, SMEM_BYTES);
  }

  // fork: weight conversions + out-init on side streams
  cudaEventRecord(evF, 0);
  cudaStreamWaitEvent(s2, evF, 0);
  cudaStreamWaitEvent(s3, evF, 0);
  cudaStreamWaitEvent(s4, evF, 0);
  convw12_kernel<<<8192, 256, 0, s2>>>((const float4*)W12);
  cudaEventRecord(ev12, s2);
  convw3_kernel<<<4096, 256, 0, s3>>>((const float4*)W3);
  cudaEventRecord(ev3, s3);
  init_kernel<<<TTOK, 256, 0, s4>>>((float4*)out);
  cudaEventRecord(evI, s4);

  // main stream: routing chain
  ln_router_kernel<<<TTOK, 256>>>(x, gamma, beta, Wr);
  hist_kernel<<<64, 256>>>();
  scan_kernel<<<1, 256>>>();
  cudaStreamWaitEvent(0, evI, 0);
  rank_kernel<<<64, 256>>>();
  cudaEventRecord(evR, 0);

  // pipeline A (experts 0-3) on stream 0
  cudaStreamWaitEvent(0, ev12, 0);
  gemm1_kernel<<<dim3(CAPACITY/128, DFF/128, 4), 256, SMEM_BYTES>>>(0);
  cudaStreamWaitEvent(0, ev3, 0);
  gemm2_kernel<<<dim3(CAPACITY/128, DMODEL/256, 4), 256, SMEM_BYTES>>>(out, 0);

  // pipeline B (experts 4-7) on s2 (convw12 already ordered in-stream)
  cudaStreamWaitEvent(s2, evR, 0);
  gemm1_kernel<<<dim3(CAPACITY/128, DFF/128, 4), 256, SMEM_BYTES, s2>>>(4);
  cudaStreamWaitEvent(s2, ev3, 0);
  gemm2_kernel<<<dim3(CAPACITY/128, DMODEL/256, 4), 256, SMEM_BYTES, s2>>>(out, 4);
  cudaEventRecord(evG2b, s2);

  // join
  cudaStreamWaitEvent(0, evG2b, 0);
}